// round 10
// baseline (speedup 1.0000x reference)
#include <cuda_runtime.h>
#include <cuda_bf16.h>
#include <cstdint>

#define BSZ 8
#define NN  256
#define DD  256
#define LN_EPS 1e-5f
#define APAD 68

typedef unsigned long long u64;

// ---------------- scratch (no allocation allowed) ----------------
__device__ __align__(16) float g_hihj[2 * BSZ * NN * DD];   // hi+0.5*b1, hj+0.5*b1
__device__ __align__(16) float g_sc  [BSZ * NN * NN];       // raw scores (diag=0, +b2)
__device__ __align__(16) float g_ctx [BSZ * NN * DD];
__device__ __align__(16) float g_proj[BSZ * NN * DD];
__device__ __align__(16) float g_mx  [BSZ * NN];            // softmax row max
__device__ __align__(16) float g_inv [BSZ * NN];            // softmax 1/sum

// ---------------- f32x2 helpers (exact fp32, packed pipe) ----------------
__device__ __forceinline__ u64 dup2(float x) {
    u64 r; asm("mov.b64 %0, {%1, %2};" : "=l"(r) : "f"(x), "f"(x)); return r;
}
__device__ __forceinline__ void fma2(u64& a, u64 b, u64 c) {
    asm("fma.rn.f32x2 %0, %1, %2, %0;" : "+l"(a) : "l"(b), "l"(c));
}
__device__ __forceinline__ u64 add2(u64 a, u64 b) {
    u64 r; asm("add.rn.f32x2 %0, %1, %2;" : "=l"(r) : "l"(a), "l"(b)); return r;
}
__device__ __forceinline__ void unpack2(u64 v, float& lo, float& hi) {
    asm("mov.b64 {%0, %1}, %2;" : "=f"(lo), "=f"(hi) : "l"(v));
}
__device__ __forceinline__ u64 relu2(u64 v) {
    float lo, hi;
    asm("mov.b64 {%0, %1}, %2;" : "=f"(lo), "=f"(hi) : "l"(v));
    lo = fmaxf(lo, 0.0f); hi = fmaxf(hi, 0.0f);
    u64 r; asm("mov.b64 %0, {%1, %2};" : "=l"(r) : "f"(lo), "f"(hi));
    return r;
}

// ---------------- GEMM: C = A @ W (+ bias*bscale) ----------------
// Tile 64(M) x 32(N) x 16(K), 256 threads, micro 4x2 (2 f32x2 row-pairs x 2 cols).
// W staged pre-duplicated: Ws2[k][n] = {w,w}. Inner loop: 2 LDS.128 + 4 FFMA2.
__global__ void __launch_bounds__(256) gemm_k(
    const float* __restrict__ A, long sA,
    const float* __restrict__ W, long sW,
    float* __restrict__ C, long sC,
    const float* __restrict__ bias, float bscale,
    int K, int Ncol)
{
    const int BK = 16;
    __shared__ __align__(16) float As[2][BK][APAD];   // transposed: As[k][m]
    __shared__ __align__(16) u64  Ws2[2][BK][32];     // dup'd: Ws2[k][n] = {w,w}

    int z = blockIdx.z;
    A += (long)z * sA;  W += (long)z * sW;  C += (long)z * sC;

    int tid = threadIdx.x;
    int tx  = tid & 15;        // col pair: cols tx*2, tx*2+1
    int tyr = tid >> 4;        // 0..15: rows tyr*4 .. +3
    int rowBase = blockIdx.x * 64;
    int colBase = blockIdx.y * 32;

    int ar = tid >> 2, ac = (tid & 3) << 2;       // A loader: 64x16, 1 float4/thread
    bool wload = tid < 128;
    int wr = tid >> 3, wc = (tid & 7) << 2;       // W loader: 16x32, 1 float4 / (128 thr)

    u64 acc[2][2] = {};

    float4 av = *(const float4*)&A[(long)(rowBase + ar) * K + ac];
    float4 wv = make_float4(0.f, 0.f, 0.f, 0.f);
    if (wload) wv = *(const float4*)&W[(long)wr * Ncol + colBase + wc];
    As[0][ac + 0][ar] = av.x; As[0][ac + 1][ar] = av.y;
    As[0][ac + 2][ar] = av.z; As[0][ac + 3][ar] = av.w;
    if (wload) {
        Ws2[0][wr][wc + 0] = dup2(wv.x); Ws2[0][wr][wc + 1] = dup2(wv.y);
        Ws2[0][wr][wc + 2] = dup2(wv.z); Ws2[0][wr][wc + 3] = dup2(wv.w);
    }
    __syncthreads();

    int buf = 0;
    for (int k0 = 0; k0 < K; k0 += BK) {
        bool more = (k0 + BK) < K;
        if (more) {
            av = *(const float4*)&A[(long)(rowBase + ar) * K + k0 + BK + ac];
            if (wload) wv = *(const float4*)&W[(long)(k0 + BK + wr) * Ncol + colBase + wc];
        }

        #pragma unroll
        for (int kk = 0; kk < BK; kk++) {
            ulonglong2 a  = *(const ulonglong2*)&As[buf][kk][tyr << 2];
            ulonglong2 wd = *(const ulonglong2*)&Ws2[buf][kk][tx << 1];
            fma2(acc[0][0], a.x, wd.x); fma2(acc[0][1], a.x, wd.y);
            fma2(acc[1][0], a.y, wd.x); fma2(acc[1][1], a.y, wd.y);
        }

        if (more) {
            int nb = buf ^ 1;
            As[nb][ac + 0][ar] = av.x; As[nb][ac + 1][ar] = av.y;
            As[nb][ac + 2][ar] = av.z; As[nb][ac + 3][ar] = av.w;
            if (wload) {
                Ws2[nb][wr][wc + 0] = dup2(wv.x); Ws2[nb][wr][wc + 1] = dup2(wv.y);
                Ws2[nb][wr][wc + 2] = dup2(wv.z); Ws2[nb][wr][wc + 3] = dup2(wv.w);
            }
        }
        __syncthreads();
        buf ^= 1;
    }

    int row0 = rowBase + (tyr << 2);
    int col  = colBase + (tx << 1);
    float bx = 0.f, by = 0.f;
    if (bias) { bx = bias[col] * bscale; by = bias[col + 1] * bscale; }

    float l00, h00, l01, h01, l10, h10, l11, h11;
    unpack2(acc[0][0], l00, h00); unpack2(acc[0][1], l01, h01);
    unpack2(acc[1][0], l10, h10); unpack2(acc[1][1], l11, h11);
    *(float2*)&C[(long)(row0 + 0) * Ncol + col] = make_float2(l00 + bx, l01 + by);
    *(float2*)&C[(long)(row0 + 1) * Ncol + col] = make_float2(h00 + bx, h01 + by);
    *(float2*)&C[(long)(row0 + 2) * Ncol + col] = make_float2(l10 + bx, l11 + by);
    *(float2*)&C[(long)(row0 + 3) * Ncol + col] = make_float2(h10 + bx, h11 + by);
}

// ---------------- pairwise relu score kernel ----------------
// scores[b,n,m] = sum_d relu(hi'[n,d] + hj'[m,d]) * W2[d] + b2   (b1 pre-folded)
// Tile 64(n) x 32(m) x 16(d), 256 threads, micro 4x2. hj + W2 staged duplicated.
__global__ void __launch_bounds__(256) scores_k(
    const float* __restrict__ W2,
    const float* __restrict__ b2)
{
    const int DK = 16;
    __shared__ __align__(16) float His[2][DK][APAD];  // [d][n]
    __shared__ __align__(16) u64  Hjs2[2][DK][32];    // [d][m] dup'd
    __shared__ u64 w2d[DD];

    int b = blockIdx.z;
    int mBase = blockIdx.x * 32;
    int nBase = blockIdx.y * 64;
    int tid = threadIdx.x;
    int tx  = tid & 15;
    int tyr = tid >> 4;

    const float* hi = g_hihj + (long)b * NN * DD;
    const float* hj = g_hihj + (long)BSZ * NN * DD + (long)b * NN * DD;

    w2d[tid] = dup2(W2[tid]);      // 256 threads cover D=256

    int ar = tid >> 2, ac = (tid & 3) << 2;        // hi loader: 64x16
    bool jload = tid < 128;
    int jr = tid >> 2, jc = (tid & 3) << 2;        // hj loader: 32x16 (tid<128)

    u64 acc[2][2] = {};

    float4 iv = *(const float4*)&hi[(long)(nBase + ar) * DD + ac];
    float4 jv = make_float4(0.f, 0.f, 0.f, 0.f);
    if (jload) jv = *(const float4*)&hj[(long)(mBase + jr) * DD + jc];
    His[0][ac + 0][ar] = iv.x; His[0][ac + 1][ar] = iv.y;
    His[0][ac + 2][ar] = iv.z; His[0][ac + 3][ar] = iv.w;
    if (jload) {
        Hjs2[0][jc + 0][jr] = dup2(jv.x); Hjs2[0][jc + 1][jr] = dup2(jv.y);
        Hjs2[0][jc + 2][jr] = dup2(jv.z); Hjs2[0][jc + 3][jr] = dup2(jv.w);
    }
    __syncthreads();

    int buf = 0;
    for (int d0 = 0; d0 < DD; d0 += DK) {
        bool more = (d0 + DK) < DD;
        if (more) {
            iv = *(const float4*)&hi[(long)(nBase + ar) * DD + d0 + DK + ac];
            if (jload) jv = *(const float4*)&hj[(long)(mBase + jr) * DD + d0 + DK + jc];
        }

        #pragma unroll
        for (int kk = 0; kk < DK; kk++) {
            ulonglong2 a  = *(const ulonglong2*)&His[buf][kk][tyr << 2];
            ulonglong2 jd = *(const ulonglong2*)&Hjs2[buf][kk][tx << 1];
            u64 wd = w2d[d0 + kk];
            fma2(acc[0][0], relu2(add2(a.x, jd.x)), wd);
            fma2(acc[0][1], relu2(add2(a.x, jd.y)), wd);
            fma2(acc[1][0], relu2(add2(a.y, jd.x)), wd);
            fma2(acc[1][1], relu2(add2(a.y, jd.y)), wd);
        }

        if (more) {
            int nb = buf ^ 1;
            His[nb][ac + 0][ar] = iv.x; His[nb][ac + 1][ar] = iv.y;
            His[nb][ac + 2][ar] = iv.z; His[nb][ac + 3][ar] = iv.w;
            if (jload) {
                Hjs2[nb][jc + 0][jr] = dup2(jv.x); Hjs2[nb][jc + 1][jr] = dup2(jv.y);
                Hjs2[nb][jc + 2][jr] = dup2(jv.z); Hjs2[nb][jc + 3][jr] = dup2(jv.w);
            }
        }
        __syncthreads();
        buf ^= 1;
    }

    const float b2v = b2[0];
    float* sc = g_sc + (long)b * NN * NN;
    int n0 = nBase + (tyr << 2);
    int m0 = mBase + (tx << 1);

    float l00, h00, l01, h01, l10, h10, l11, h11;
    unpack2(acc[0][0], l00, h00); unpack2(acc[0][1], l01, h01);
    unpack2(acc[1][0], l10, h10); unpack2(acc[1][1], l11, h11);
    {
        int n = n0;
        *(float2*)&sc[(long)n * NN + m0] = make_float2(
            (n == m0) ? 0.f : l00 + b2v, (n == m0 + 1) ? 0.f : l01 + b2v);
        n = n0 + 1;
        *(float2*)&sc[(long)n * NN + m0] = make_float2(
            (n == m0) ? 0.f : h00 + b2v, (n == m0 + 1) ? 0.f : h01 + b2v);
        n = n0 + 2;
        *(float2*)&sc[(long)n * NN + m0] = make_float2(
            (n == m0) ? 0.f : l10 + b2v, (n == m0 + 1) ? 0.f : l11 + b2v);
        n = n0 + 3;
        *(float2*)&sc[(long)n * NN + m0] = make_float2(
            (n == m0) ? 0.f : h10 + b2v, (n == m0 + 1) ? 0.f : h11 + b2v);
    }
}

// ---------------- softmax row stats: max & 1/sum(exp) per row ----------------
__global__ void __launch_bounds__(256) stats_k()
{
    int row = blockIdx.x * 8 + (threadIdx.x >> 5);   // b*N + n
    int lane = threadIdx.x & 31;
    const float* r = g_sc + (long)row * NN;
    float4 v0 = *(const float4*)&r[lane * 8];
    float4 v1 = *(const float4*)&r[lane * 8 + 4];
    float mx = fmaxf(fmaxf(fmaxf(v0.x, v0.y), fmaxf(v0.z, v0.w)),
                     fmaxf(fmaxf(v1.x, v1.y), fmaxf(v1.z, v1.w)));
    #pragma unroll
    for (int o = 16; o > 0; o >>= 1) mx = fmaxf(mx, __shfl_xor_sync(0xffffffffu, mx, o));
    float s = __expf(v0.x - mx) + __expf(v0.y - mx) + __expf(v0.z - mx) + __expf(v0.w - mx)
            + __expf(v1.x - mx) + __expf(v1.y - mx) + __expf(v1.z - mx) + __expf(v1.w - mx);
    #pragma unroll
    for (int o = 16; o > 0; o >>= 1) s += __shfl_xor_sync(0xffffffffu, s, o);
    if (lane == 0) { g_mx[row] = mx; g_inv[row] = 1.0f / s; }
}

// ---------------- fused softmax + ctx GEMM ----------------
// ctx[b,n,:] = (sum_m exp(sc[n,m]-mx[n]) * x[m,:]) * inv[n]
// Same 64x32 tile structure; exp applied during A staging.
__global__ void __launch_bounds__(256) ctx_k(const float* __restrict__ x)
{
    const int BK = 16;
    __shared__ __align__(16) float As[2][BK][APAD];
    __shared__ __align__(16) u64  Ws2[2][BK][32];

    int b = blockIdx.z;
    int nBase = blockIdx.x * 64;
    int colBase = blockIdx.y * 32;
    int tid = threadIdx.x;
    int tx  = tid & 15;
    int tyr = tid >> 4;

    const float* sc = g_sc + (long)b * NN * NN;
    const float* X  = x + (long)b * NN * DD;

    int ar = tid >> 2, ac = (tid & 3) << 2;
    bool wload = tid < 128;
    int wr = tid >> 3, wc = (tid & 7) << 2;

    // FIX (R9): stats are indexed by the GLOBAL row b*NN + n, not just n.
    float rmx = g_mx[(long)b * NN + nBase + ar];
    u64 acc[2][2] = {};

    float4 av = *(const float4*)&sc[(long)(nBase + ar) * NN + ac];
    float4 wv = make_float4(0.f, 0.f, 0.f, 0.f);
    if (wload) wv = *(const float4*)&X[(long)wr * DD + colBase + wc];
    As[0][ac + 0][ar] = __expf(av.x - rmx); As[0][ac + 1][ar] = __expf(av.y - rmx);
    As[0][ac + 2][ar] = __expf(av.z - rmx); As[0][ac + 3][ar] = __expf(av.w - rmx);
    if (wload) {
        Ws2[0][wr][wc + 0] = dup2(wv.x); Ws2[0][wr][wc + 1] = dup2(wv.y);
        Ws2[0][wr][wc + 2] = dup2(wv.z); Ws2[0][wr][wc + 3] = dup2(wv.w);
    }
    __syncthreads();

    int buf = 0;
    for (int k0 = 0; k0 < NN; k0 += BK) {
        bool more = (k0 + BK) < NN;
        if (more) {
            av = *(const float4*)&sc[(long)(nBase + ar) * NN + k0 + BK + ac];
            if (wload) wv = *(const float4*)&X[(long)(k0 + BK + wr) * DD + colBase + wc];
        }

        #pragma unroll
        for (int kk = 0; kk < BK; kk++) {
            ulonglong2 a  = *(const ulonglong2*)&As[buf][kk][tyr << 2];
            ulonglong2 wd = *(const ulonglong2*)&Ws2[buf][kk][tx << 1];
            fma2(acc[0][0], a.x, wd.x); fma2(acc[0][1], a.x, wd.y);
            fma2(acc[1][0], a.y, wd.x); fma2(acc[1][1], a.y, wd.y);
        }

        if (more) {
            int nb = buf ^ 1;
            As[nb][ac + 0][ar] = __expf(av.x - rmx); As[nb][ac + 1][ar] = __expf(av.y - rmx);
            As[nb][ac + 2][ar] = __expf(av.z - rmx); As[nb][ac + 3][ar] = __expf(av.w - rmx);
            if (wload) {
                Ws2[nb][wr][wc + 0] = dup2(wv.x); Ws2[nb][wr][wc + 1] = dup2(wv.y);
                Ws2[nb][wr][wc + 2] = dup2(wv.z); Ws2[nb][wr][wc + 3] = dup2(wv.w);
            }
        }
        __syncthreads();
        buf ^= 1;
    }

    float* ctx = g_ctx + (long)b * NN * DD;
    int row0 = nBase + (tyr << 2);
    int col  = colBase + (tx << 1);
    // FIX (R9): global-row indexing for inv as well.
    float4 iv = *(const float4*)&g_inv[(long)b * NN + row0];

    float l00, h00, l01, h01, l10, h10, l11, h11;
    unpack2(acc[0][0], l00, h00); unpack2(acc[0][1], l01, h01);
    unpack2(acc[1][0], l10, h10); unpack2(acc[1][1], l11, h11);
    *(float2*)&ctx[(long)(row0 + 0) * DD + col] = make_float2(l00 * iv.x, l01 * iv.x);
    *(float2*)&ctx[(long)(row0 + 1) * DD + col] = make_float2(h00 * iv.y, h01 * iv.y);
    *(float2*)&ctx[(long)(row0 + 2) * DD + col] = make_float2(l10 * iv.z, l11 * iv.z);
    *(float2*)&ctx[(long)(row0 + 3) * DD + col] = make_float2(h10 * iv.w, h11 * iv.w);
}

// ---------------- LayerNorm + residual ----------------
__global__ void ln_res_k(const float* __restrict__ x,
                         const float* __restrict__ gamma,
                         const float* __restrict__ beta,
                         float* __restrict__ out)
{
    __shared__ float red[8];
    int row = blockIdx.x;
    int tid = threadIdx.x;
    int wid = tid >> 5, lane = tid & 31;

    float p = g_proj[(long)row * DD + tid];

    float s = p;
    #pragma unroll
    for (int o = 16; o > 0; o >>= 1) s += __shfl_xor_sync(0xffffffffu, s, o);
    if (lane == 0) red[wid] = s;
    __syncthreads();
    float tot = 0.0f;
    #pragma unroll
    for (int w = 0; w < 8; w++) tot += red[w];
    float mean = tot * (1.0f / DD);

    float dv = p - mean;
    float q = dv * dv;
    #pragma unroll
    for (int o = 16; o > 0; o >>= 1) q += __shfl_xor_sync(0xffffffffu, q, o);
    __syncthreads();
    if (lane == 0) red[wid] = q;
    __syncthreads();
    float tq = 0.0f;
    #pragma unroll
    for (int w = 0; w < 8; w++) tq += red[w];
    float var = tq * (1.0f / DD);

    float inv = rsqrtf(var + LN_EPS);
    out[(long)row * DD + tid] = x[(long)row * DD + tid] + dv * inv * gamma[tid] + beta[tid];
}

// ---------------- launch ----------------
extern "C" void kernel_launch(void* const* d_in, const int* in_sizes, int n_in,
                              void* d_out, int out_size)
{
    const float* x     = (const float*)d_in[0];  // [B,N,D]
    const float* W1    = (const float*)d_in[1];  // [2D,D]
    const float* b1    = (const float*)d_in[2];  // [D]
    const float* W2    = (const float*)d_in[3];  // [D,1]
    const float* b2    = (const float*)d_in[4];  // [1]
    const float* Wp    = (const float*)d_in[5];  // [D,D]
    const float* bp    = (const float*)d_in[6];  // [D]
    const float* gamma = (const float*)d_in[7];  // [D]
    const float* beta  = (const float*)d_in[8];  // [D]
    float* out = (float*)d_out;

    float *hihj, *ctx, *proj;
    cudaGetSymbolAddress((void**)&hihj, g_hihj);
    cudaGetSymbolAddress((void**)&ctx,  g_ctx);
    cudaGetSymbolAddress((void**)&proj, g_proj);

    // 1) hi' = x @ W1[:D] + 0.5*b1 ; hj' = x @ W1[D:] + 0.5*b1   (512 CTAs)
    gemm_k<<<dim3((BSZ * NN) / 64, DD / 32, 2), 256>>>(
        x, 0L, W1, (long)DD * DD, hihj, (long)BSZ * NN * DD,
        b1, 0.5f, DD, DD);

    // 2) pairwise relu scores (+b2, diag=0)                       (256 CTAs)
    scores_k<<<dim3(NN / 32, NN / 64, BSZ), 256>>>(W2, b2);

    // 3) softmax row stats                                        (256 CTAs)
    stats_k<<<(BSZ * NN) / 8, 256>>>();

    // 4) fused softmax + ctx GEMM                                 (256 CTAs)
    ctx_k<<<dim3(NN / 64, DD / 32, BSZ), 256>>>(x);

    // 5) proj = ctx @ Wp + bp                                     (256 CTAs)
    gemm_k<<<dim3((BSZ * NN) / 64, DD / 32, 1), 256>>>(
        ctx, 0L, Wp, 0L, proj, 0L,
        bp, 1.0f, DD, DD);

    // 6) out = x + LN(proj)
    ln_res_k<<<BSZ * NN, 256>>>(x, gamma, beta, out);
}

// round 13
// speedup vs baseline: 1.5960x; 1.5960x over previous
#include <cuda_runtime.h>
#include <cuda_bf16.h>
#include <cstdint>

#define BSZ 8
#define NN  256
#define DD  256
#define LN_EPS 1e-5f
#define APAD 68
#define SLAB_SC (BSZ * NN * NN)
#define SLAB_CD (BSZ * NN * DD)

typedef unsigned long long u64;

// ---------------- scratch (no allocation allowed) ----------------
__device__ __align__(16) float g_hihj [2 * BSZ * NN * DD];  // hi+0.5b1 | hj+0.5b1
__device__ __align__(16) float g_scP  [2 * BSZ * NN * NN];  // score partials -> exp'd scores (slab0)
__device__ __align__(16) float g_ctxP [2 * BSZ * NN * DD];  // ctx partials -> combined (slab0)
__device__ __align__(16) float g_projP[2 * BSZ * NN * DD];  // proj partials
__device__ __align__(16) float g_inv  [BSZ * NN];           // softmax 1/sum

// ---------------- f32x2 helpers (exact fp32, packed pipe) ----------------
__device__ __forceinline__ u64 dup2(float x) {
    u64 r; asm("mov.b64 %0, {%1, %2};" : "=l"(r) : "f"(x), "f"(x)); return r;
}
__device__ __forceinline__ void fma2(u64& a, u64 b, u64 c) {
    asm("fma.rn.f32x2 %0, %1, %2, %0;" : "+l"(a) : "l"(b), "l"(c));
}
__device__ __forceinline__ u64 add2(u64 a, u64 b) {
    u64 r; asm("add.rn.f32x2 %0, %1, %2;" : "=l"(r) : "l"(a), "l"(b)); return r;
}
__device__ __forceinline__ void unpack2(u64 v, float& lo, float& hi) {
    asm("mov.b64 {%0, %1}, %2;" : "=f"(lo), "=f"(hi) : "l"(v));
}
__device__ __forceinline__ u64 relu2(u64 v) {
    float lo, hi;
    asm("mov.b64 {%0, %1}, %2;" : "=f"(lo), "=f"(hi) : "l"(v));
    lo = fmaxf(lo, 0.0f); hi = fmaxf(hi, 0.0f);
    u64 r; asm("mov.b64 %0, {%1, %2};" : "=l"(r) : "f"(lo), "f"(hi));
    return r;
}

// ---------------- generic GEMM: C = A @ W (+ bias*bscale) ----------------
// Tile 64x64x16, 256 threads, micro 4x4 (R6 inner), depth-2 register pipeline.
// ksplit=1: blockIdx.y = half*4 + colTile; A/W/C shifted by half*K cols / rows / halfC.
__global__ void __launch_bounds__(256) gemm_k(
    const float* __restrict__ A, long sA, int lda,
    const float* __restrict__ W, long sW,
    float* __restrict__ C, long sC, long halfC,
    const float* __restrict__ bias, float bscale,
    int K, int Ncol, int ksplit)
{
    const int BK = 16;
    __shared__ __align__(16) float As[2][BK][APAD];   // transposed: As[k][m]
    __shared__ __align__(16) float Ws[2][BK][64];     // Ws[k][n]

    int z = blockIdx.z;
    A += (long)z * sA;  W += (long)z * sW;  C += (long)z * sC;

    int colBase;
    if (ksplit) {
        int half = blockIdx.y >> 2;
        colBase = (blockIdx.y & 3) * 64;
        A += half * K;                       // K cols within lda-wide rows
        W += (long)half * K * Ncol;          // K rows
        C += half * halfC;                   // partial slab
    } else {
        colBase = blockIdx.y * 64;
    }
    int rowBase = blockIdx.x * 64;

    int tid = threadIdx.x;
    int tx  = tid & 15;
    int tyr = tid >> 4;
    int ar = tid >> 2, ac = (tid & 3) << 2;
    int wr = tid >> 4, wc = (tid & 15) << 2;

    const float* Ap = A + (long)(rowBase + ar) * lda + ac;
    const float* Wq = W + (long)wr * Ncol + colBase + wc;
    const int NC = K / BK;                   // even (8 or 16)

    u64 acc[2][4] = {};

    float4 a0 = *(const float4*)Ap;
    float4 w0 = *(const float4*)Wq;
    float4 a1 = *(const float4*)(Ap + BK);
    float4 w1 = *(const float4*)(Wq + (long)BK * Ncol);

    As[0][ac + 0][ar] = a0.x; As[0][ac + 1][ar] = a0.y;
    As[0][ac + 2][ar] = a0.z; As[0][ac + 3][ar] = a0.w;
    *(float4*)&Ws[0][wr][wc] = w0;
    __syncthreads();

#define G_STEP(BUF)                                                        \
    _Pragma("unroll")                                                      \
    for (int kk = 0; kk < BK; kk++) {                                      \
        ulonglong2 a = *(const ulonglong2*)&As[BUF][kk][tyr << 2];         \
        float4 w4 = *(const float4*)&Ws[BUF][kk][tx << 2];                 \
        u64 wd0 = dup2(w4.x), wd1 = dup2(w4.y);                            \
        u64 wd2 = dup2(w4.z), wd3 = dup2(w4.w);                            \
        fma2(acc[0][0], a.x, wd0); fma2(acc[0][1], a.x, wd1);              \
        fma2(acc[0][2], a.x, wd2); fma2(acc[0][3], a.x, wd3);              \
        fma2(acc[1][0], a.y, wd0); fma2(acc[1][1], a.y, wd1);              \
        fma2(acc[1][2], a.y, wd2); fma2(acc[1][3], a.y, wd3);              \
    }

    for (int c = 0; c < NC; c += 2) {
        // even chunk c  (buf0); prefetch c+2 into slot0; stage c+1 -> buf1
        if (c + 2 < NC) {
            a0 = *(const float4*)(Ap + (c + 2) * BK);
            w0 = *(const float4*)(Wq + (long)(c + 2) * BK * Ncol);
        }
        As[1][ac + 0][ar] = a1.x; As[1][ac + 1][ar] = a1.y;
        As[1][ac + 2][ar] = a1.z; As[1][ac + 3][ar] = a1.w;
        *(float4*)&Ws[1][wr][wc] = w1;
        G_STEP(0)
        __syncthreads();

        // odd chunk c+1 (buf1); prefetch c+3 into slot1; stage c+2 -> buf0
        if (c + 3 < NC) {
            a1 = *(const float4*)(Ap + (c + 3) * BK);
            w1 = *(const float4*)(Wq + (long)(c + 3) * BK * Ncol);
        }
        if (c + 2 < NC) {
            As[0][ac + 0][ar] = a0.x; As[0][ac + 1][ar] = a0.y;
            As[0][ac + 2][ar] = a0.z; As[0][ac + 3][ar] = a0.w;
            *(float4*)&Ws[0][wr][wc] = w0;
        }
        G_STEP(1)
        __syncthreads();
    }
#undef G_STEP

    int row0 = rowBase + (tyr << 2);
    int col  = colBase + (tx << 2);
    float4 bv = make_float4(0.f, 0.f, 0.f, 0.f);
    if (bias) {
        bv = *(const float4*)&bias[col];
        bv.x *= bscale; bv.y *= bscale; bv.z *= bscale; bv.w *= bscale;
    }

    #pragma unroll
    for (int p = 0; p < 2; p++) {
        float e0, o0, e1, o1, e2, o2, e3, o3;
        unpack2(acc[p][0], e0, o0); unpack2(acc[p][1], e1, o1);
        unpack2(acc[p][2], e2, o2); unpack2(acc[p][3], e3, o3);
        *(float4*)&C[(long)(row0 + 2 * p + 0) * Ncol + col] =
            make_float4(e0 + bv.x, e1 + bv.y, e2 + bv.z, e3 + bv.w);
        *(float4*)&C[(long)(row0 + 2 * p + 1) * Ncol + col] =
            make_float4(o0 + bv.x, o1 + bv.y, o2 + bv.z, o3 + bv.w);
    }
}

// ---------------- pairwise relu score PARTIAL kernel ----------------
// partial[b,n,m] = sum_{d in half} relu(hi'[n,d] + hj'[m,d]) * W2[d]
// (b1 pre-folded into hi'/hj'; b2 + diag handled in stats_k)
__global__ void __launch_bounds__(256) scores_k(const float* __restrict__ W2)
{
    const int BK = 16;
    const int KH = DD / 2;                   // 128 d per half
    __shared__ __align__(16) float His[2][BK][APAD];  // [d][n]
    __shared__ __align__(16) float Hjs[2][BK][64];    // [d][m]
    __shared__ float w2s[KH];

    int b = blockIdx.z;
    int half = blockIdx.y >> 2;
    int nBase = (blockIdx.y & 3) * 64;
    int mBase = blockIdx.x * 64;
    int d0 = half * KH;

    int tid = threadIdx.x;
    int tx  = tid & 15;
    int tyr = tid >> 4;

    const float* hi = g_hihj + (long)b * NN * DD + d0;
    const float* hj = g_hihj + (long)SLAB_CD + (long)b * NN * DD + d0;
    if (tid < KH) w2s[tid] = W2[d0 + tid];

    int ar = tid >> 2, ac = (tid & 3) << 2;
    const float* Ip = hi + (long)(nBase + ar) * DD + ac;
    const float* Jp = hj + (long)(mBase + ar) * DD + ac;
    const int NC = KH / BK;                  // 8

    u64 acc[2][4] = {};

    float4 i0 = *(const float4*)Ip;
    float4 j0 = *(const float4*)Jp;
    float4 i1 = *(const float4*)(Ip + BK);
    float4 j1 = *(const float4*)(Jp + BK);

    His[0][ac + 0][ar] = i0.x; His[0][ac + 1][ar] = i0.y;
    His[0][ac + 2][ar] = i0.z; His[0][ac + 3][ar] = i0.w;
    Hjs[0][ac + 0][ar] = j0.x; Hjs[0][ac + 1][ar] = j0.y;
    Hjs[0][ac + 2][ar] = j0.z; Hjs[0][ac + 3][ar] = j0.w;
    __syncthreads();

#define S_STEP(BUF, CC)                                                    \
    _Pragma("unroll")                                                      \
    for (int kk = 0; kk < BK; kk++) {                                      \
        ulonglong2 a = *(const ulonglong2*)&His[BUF][kk][tyr << 2];        \
        float4 j4 = *(const float4*)&Hjs[BUF][kk][tx << 2];                \
        u64 jd0 = dup2(j4.x), jd1 = dup2(j4.y);                            \
        u64 jd2 = dup2(j4.z), jd3 = dup2(j4.w);                            \
        u64 wd = dup2(w2s[(CC) * BK + kk]);                                \
        fma2(acc[0][0], relu2(add2(a.x, jd0)), wd);                        \
        fma2(acc[0][1], relu2(add2(a.x, jd1)), wd);                        \
        fma2(acc[0][2], relu2(add2(a.x, jd2)), wd);                        \
        fma2(acc[0][3], relu2(add2(a.x, jd3)), wd);                        \
        fma2(acc[1][0], relu2(add2(a.y, jd0)), wd);                        \
        fma2(acc[1][1], relu2(add2(a.y, jd1)), wd);                        \
        fma2(acc[1][2], relu2(add2(a.y, jd2)), wd);                        \
        fma2(acc[1][3], relu2(add2(a.y, jd3)), wd);                        \
    }

    for (int c = 0; c < NC; c += 2) {
        if (c + 2 < NC) {
            i0 = *(const float4*)(Ip + (c + 2) * BK);
            j0 = *(const float4*)(Jp + (c + 2) * BK);
        }
        His[1][ac + 0][ar] = i1.x; His[1][ac + 1][ar] = i1.y;
        His[1][ac + 2][ar] = i1.z; His[1][ac + 3][ar] = i1.w;
        Hjs[1][ac + 0][ar] = j1.x; Hjs[1][ac + 1][ar] = j1.y;
        Hjs[1][ac + 2][ar] = j1.z; Hjs[1][ac + 3][ar] = j1.w;
        S_STEP(0, c)
        __syncthreads();

        if (c + 3 < NC) {
            i1 = *(const float4*)(Ip + (c + 3) * BK);
            j1 = *(const float4*)(Jp + (c + 3) * BK);
        }
        if (c + 2 < NC) {
            His[0][ac + 0][ar] = i0.x; His[0][ac + 1][ar] = i0.y;
            His[0][ac + 2][ar] = i0.z; His[0][ac + 3][ar] = i0.w;
            Hjs[0][ac + 0][ar] = j0.x; Hjs[0][ac + 1][ar] = j0.y;
            Hjs[0][ac + 2][ar] = j0.z; Hjs[0][ac + 3][ar] = j0.w;
        }
        S_STEP(1, c + 1)
        __syncthreads();
    }
#undef S_STEP

    float* dst = g_scP + (long)half * SLAB_SC + (long)b * NN * NN;
    int n0 = nBase + (tyr << 2);
    int m0 = mBase + (tx << 2);

    #pragma unroll
    for (int p = 0; p < 2; p++) {
        float e0, o0, e1, o1, e2, o2, e3, o3;
        unpack2(acc[p][0], e0, o0); unpack2(acc[p][1], e1, o1);
        unpack2(acc[p][2], e2, o2); unpack2(acc[p][3], e3, o3);
        *(float4*)&dst[(long)(n0 + 2 * p + 0) * NN + m0] = make_float4(e0, e1, e2, e3);
        *(float4*)&dst[(long)(n0 + 2 * p + 1) * NN + m0] = make_float4(o0, o1, o2, o3);
    }
}

// ---------------- stats: combine halves (+b2, diag=0), write exp'd row + 1/sum ----------------
__global__ void __launch_bounds__(256) stats_k(const float* __restrict__ b2)
{
    int wid = threadIdx.x >> 5, lane = threadIdx.x & 31;
    int row = blockIdx.x * 8 + wid;          // b*N + n, 2048 rows
    float* p0 = g_scP + (long)row * NN;
    const float* p1 = g_scP + (long)SLAB_SC + (long)row * NN;
    float b2v = b2[0];
    int m0 = lane * 8;

    float4 u0 = *(const float4*)(p0 + m0);
    float4 u1 = *(const float4*)(p0 + m0 + 4);
    float4 v0 = *(const float4*)(p1 + m0);
    float4 v1 = *(const float4*)(p1 + m0 + 4);

    float s0 = u0.x + v0.x + b2v, s1 = u0.y + v0.y + b2v;
    float s2 = u0.z + v0.z + b2v, s3 = u0.w + v0.w + b2v;
    float s4 = u1.x + v1.x + b2v, s5 = u1.y + v1.y + b2v;
    float s6 = u1.z + v1.z + b2v, s7 = u1.w + v1.w + b2v;

    int n = row & (NN - 1);
    if (n == m0 + 0) s0 = 0.0f;  if (n == m0 + 1) s1 = 0.0f;
    if (n == m0 + 2) s2 = 0.0f;  if (n == m0 + 3) s3 = 0.0f;
    if (n == m0 + 4) s4 = 0.0f;  if (n == m0 + 5) s5 = 0.0f;
    if (n == m0 + 6) s6 = 0.0f;  if (n == m0 + 7) s7 = 0.0f;

    float mx = fmaxf(fmaxf(fmaxf(s0, s1), fmaxf(s2, s3)),
                     fmaxf(fmaxf(s4, s5), fmaxf(s6, s7)));
    #pragma unroll
    for (int o = 16; o > 0; o >>= 1) mx = fmaxf(mx, __shfl_xor_sync(0xffffffffu, mx, o));

    float e0 = __expf(s0 - mx), e1 = __expf(s1 - mx), e2 = __expf(s2 - mx), e3 = __expf(s3 - mx);
    float e4 = __expf(s4 - mx), e5 = __expf(s5 - mx), e6 = __expf(s6 - mx), e7 = __expf(s7 - mx);
    float s = e0 + e1 + e2 + e3 + e4 + e5 + e6 + e7;
    #pragma unroll
    for (int o = 16; o > 0; o >>= 1) s += __shfl_xor_sync(0xffffffffu, s, o);

    *(float4*)(p0 + m0)     = make_float4(e0, e1, e2, e3);
    *(float4*)(p0 + m0 + 4) = make_float4(e4, e5, e6, e7);
    if (lane == 0) g_inv[row] = 1.0f / s;
}

// ---------------- combine ctx halves + apply 1/sum ----------------
__global__ void __launch_bounds__(256) combine_k()
{
    long e = ((long)blockIdx.x * 256 + threadIdx.x) * 4;   // over BSZ*NN*DD
    int row = (int)(e >> 8);                               // DD = 256
    float inv = g_inv[row];
    float4 u = *(const float4*)(g_ctxP + e);
    float4 v = *(const float4*)(g_ctxP + (long)SLAB_CD + e);
    u.x = (u.x + v.x) * inv; u.y = (u.y + v.y) * inv;
    u.z = (u.z + v.z) * inv; u.w = (u.w + v.w) * inv;
    *(float4*)(g_ctxP + e) = u;
}

// ---------------- combine proj halves + bias + LayerNorm + residual ----------------
__global__ void __launch_bounds__(256) ln_res_k(
    const float* __restrict__ x,
    const float* __restrict__ bp,
    const float* __restrict__ gamma,
    const float* __restrict__ beta,
    float* __restrict__ out)
{
    __shared__ float red[8];
    int row = blockIdx.x;
    int tid = threadIdx.x;
    int wid = tid >> 5, lane = tid & 31;

    float p = g_projP[(long)row * DD + tid]
            + g_projP[(long)SLAB_CD + (long)row * DD + tid]
            + bp[tid];

    float s = p;
    #pragma unroll
    for (int o = 16; o > 0; o >>= 1) s += __shfl_xor_sync(0xffffffffu, s, o);
    if (lane == 0) red[wid] = s;
    __syncthreads();
    float tot = 0.0f;
    #pragma unroll
    for (int w = 0; w < 8; w++) tot += red[w];
    float mean = tot * (1.0f / DD);

    float dv = p - mean;
    float q = dv * dv;
    #pragma unroll
    for (int o = 16; o > 0; o >>= 1) q += __shfl_xor_sync(0xffffffffu, q, o);
    __syncthreads();
    if (lane == 0) red[wid] = q;
    __syncthreads();
    float tq = 0.0f;
    #pragma unroll
    for (int w = 0; w < 8; w++) tq += red[w];
    float var = tq * (1.0f / DD);

    float inv = rsqrtf(var + LN_EPS);
    out[(long)row * DD + tid] = x[(long)row * DD + tid] + dv * inv * gamma[tid] + beta[tid];
}

// ---------------- launch ----------------
extern "C" void kernel_launch(void* const* d_in, const int* in_sizes, int n_in,
                              void* d_out, int out_size)
{
    const float* x     = (const float*)d_in[0];  // [B,N,D]
    const float* W1    = (const float*)d_in[1];  // [2D,D]
    const float* b1    = (const float*)d_in[2];  // [D]
    const float* W2    = (const float*)d_in[3];  // [D,1]
    const float* b2    = (const float*)d_in[4];  // [1]
    const float* Wp    = (const float*)d_in[5];  // [D,D]
    const float* bp    = (const float*)d_in[6];  // [D]
    const float* gamma = (const float*)d_in[7];  // [D]
    const float* beta  = (const float*)d_in[8];  // [D]
    float* out = (float*)d_out;

    float *hihj, *scP, *ctxP, *projP;
    cudaGetSymbolAddress((void**)&hihj,  g_hihj);
    cudaGetSymbolAddress((void**)&scP,   g_scP);
    cudaGetSymbolAddress((void**)&ctxP,  g_ctxP);
    cudaGetSymbolAddress((void**)&projP, g_projP);

    // 1) hi' = x @ W1[:D] + 0.5*b1 ; hj' = x @ W1[D:] + 0.5*b1   (grid 32x4x2 = 256)
    gemm_k<<<dim3(32, 4, 2), 256>>>(
        x, 0L, DD, W1, (long)DD * DD, hihj, (long)SLAB_CD, 0L,
        b1, 0.5f, DD, DD, 0);

    // 2) score partials, d split in blockIdx.y                    (grid 4x8x8 = 256)
    scores_k<<<dim3(4, 8, 8), 256>>>(W2);

    // 3) combine + b2 + diag + exp'd scores + 1/sum               (grid 256)
    stats_k<<<(BSZ * NN) / 8, 256>>>(b2);

    // 4) ctx partials = exp'd @ x, m split                        (grid 4x8x8 = 256)
    gemm_k<<<dim3(4, 8, 8), 256>>>(
        scP, (long)NN * NN, NN, x, (long)NN * DD,
        ctxP, (long)NN * DD, (long)SLAB_CD,
        nullptr, 0.0f, NN / 2, DD, 1);

    // 5) combine ctx halves * inv                                 (grid 512)
    combine_k<<<(BSZ * NN * DD) / (256 * 4), 256>>>();

    // 6) proj partials = ctx @ Wp, k split                        (grid 32x8x1 = 256)
    gemm_k<<<dim3(32, 8, 1), 256>>>(
        ctxP, 0L, DD, Wp, 0L,
        projP, 0L, (long)SLAB_CD,
        nullptr, 0.0f, DD / 2, DD, 1);

    // 7) combine proj halves + bp + LN + residual                 (grid 2048)
    ln_res_k<<<BSZ * NN, 256>>>(x, bp, gamma, beta, out);
}

// round 16
// speedup vs baseline: 1.6535x; 1.0360x over previous
#include <cuda_runtime.h>
#include <cuda_bf16.h>
#include <cstdint>

#define BSZ 8
#define NN  256
#define DD  256
#define LN_EPS 1e-5f
#define APAD 68
#define SLAB_SC (BSZ * NN * NN)
#define SLAB_CD (BSZ * NN * DD)

typedef unsigned long long u64;

// ---------------- scratch (no allocation allowed) ----------------
__device__ __align__(16) float g_hihj [2 * BSZ * NN * DD];  // hi+0.5b1 | hj+0.5b1
__device__ __align__(16) float g_scP  [2 * BSZ * NN * NN];  // score partials -> exp'd scores (slab0)
__device__ __align__(16) float g_ctxP [2 * BSZ * NN * DD];  // ctx partials -> combined (slab0)
__device__ __align__(16) float g_projP[2 * BSZ * NN * DD];  // proj partials
__device__ __align__(16) float g_inv  [BSZ * NN];           // softmax 1/sum

// ---------------- f32x2 helpers (scores kernel) ----------------
__device__ __forceinline__ u64 dup2(float x) {
    u64 r; asm("mov.b64 %0, {%1, %2};" : "=l"(r) : "f"(x), "f"(x)); return r;
}
__device__ __forceinline__ void fma2(u64& a, u64 b, u64 c) {
    asm("fma.rn.f32x2 %0, %1, %2, %0;" : "+l"(a) : "l"(b), "l"(c));
}
__device__ __forceinline__ u64 add2(u64 a, u64 b) {
    u64 r; asm("add.rn.f32x2 %0, %1, %2;" : "=l"(r) : "l"(a), "l"(b)); return r;
}
__device__ __forceinline__ void unpack2(u64 v, float& lo, float& hi) {
    asm("mov.b64 {%0, %1}, %2;" : "=f"(lo), "=f"(hi) : "l"(v));
}
__device__ __forceinline__ u64 relu2(u64 v) {
    float lo, hi;
    asm("mov.b64 {%0, %1}, %2;" : "=f"(lo), "=f"(hi) : "l"(v));
    lo = fmaxf(lo, 0.0f); hi = fmaxf(hi, 0.0f);
    u64 r; asm("mov.b64 %0, {%1, %2};" : "=l"(r) : "f"(lo), "f"(hi));
    return r;
}

// ================= tensor-core GEMM (tf32 split precision) =================
// C = A @ W (+ bias*bscale).  Tile 128(M) x 64(N) x 16(K), 256 threads,
// warps 4(m) x 2(n) each 32x32 via mma.m16n8k8.  A staged [128][20] row-major
// (conflict-free frag reads), B staged transposed [64][17].
// Split: v = hi + lo (both tf32); A@B ~= Ah@Bh + Ah@Bl + Al@Bh.

#define CVT_HILO(v, hb, lb) {                                              \
    asm("cvt.rna.tf32.f32 %0, %1;" : "=r"(hb) : "f"(v));                   \
    float _lo = (v) - __uint_as_float(hb);                                 \
    asm("cvt.rna.tf32.f32 %0, %1;" : "=r"(lb) : "f"(_lo)); }

#define MMA8(c, a, b)                                                      \
    asm volatile("mma.sync.aligned.m16n8k8.row.col.f32.tf32.tf32.f32 "     \
        "{%0,%1,%2,%3}, {%4,%5,%6,%7}, {%8,%9}, {%0,%1,%2,%3};"            \
        : "+f"((c)[0]), "+f"((c)[1]), "+f"((c)[2]), "+f"((c)[3])           \
        : "r"((a)[0]), "r"((a)[1]), "r"((a)[2]), "r"((a)[3]),              \
          "r"((b)[0]), "r"((b)[1]));

__global__ void __launch_bounds__(256) gemm_t(
    const float* __restrict__ A, long sAb, int lda,
    const float* __restrict__ W, long sWb,
    float* __restrict__ C, long sCb, long halfC,
    const float* __restrict__ bias, float bscale,
    int K, int Ncol, int ksplit)
{
    __shared__ float sA[2][128][20];   // [plane][row][k]  (20: bank-perfect frags)
    __shared__ float sB[2][64][17];    // [plane][n][k]    (17: <=2-way)

    int z = blockIdx.z;
    A += (long)z * sAb;  W += (long)z * sWb;  C += (long)z * sCb;

    int colBase;
    if (ksplit) {
        int half = blockIdx.y >> 2;
        colBase = (blockIdx.y & 3) * 64;
        A += half * K;
        W += (long)half * K * Ncol;
        C += half * halfC;
    } else colBase = blockIdx.y * 64;
    int rowBase = blockIdx.x * 128;

    int tid  = threadIdx.x;
    int lane = tid & 31, wid = tid >> 5;
    int wm = wid & 3;                       // 0..3: m-tile of 32
    int wn = wid >> 2;                      // 0..1: n-tile of 32
    int lr = lane >> 2, lc = lane & 3;

    // staging indices: A 128x16 = 512 float4 (2/thread); B 16x64 = 256 float4 (1/thread)
    int ar0 = tid >> 2,         ac0 = (tid & 3) << 2;
    int ar1 = (tid + 256) >> 2, ac1 = ac0;
    int bk  = tid >> 4,         bn4 = (tid & 15) << 2;

    const float* Ag0 = A + (long)(rowBase + ar0) * lda + ac0;
    const float* Ag1 = A + (long)(rowBase + ar1) * lda + ac1;
    const float* Bg  = W + (long)bk * Ncol + colBase + bn4;

    const int NC = K >> 4;

    float acc[2][4][4];
    #pragma unroll
    for (int i = 0; i < 2; i++)
        #pragma unroll
        for (int j = 0; j < 4; j++)
            #pragma unroll
            for (int q = 0; q < 4; q++) acc[i][j][q] = 0.0f;

    float4 pa0 = *(const float4*)Ag0;
    float4 pa1 = *(const float4*)Ag1;
    float4 pb  = *(const float4*)Bg;

#define STAGE() {                                                          \
    uint32_t hx,hy,hz,hw,lx,ly,lz,lw;                                      \
    CVT_HILO(pa0.x,hx,lx) CVT_HILO(pa0.y,hy,ly)                            \
    CVT_HILO(pa0.z,hz,lz) CVT_HILO(pa0.w,hw,lw)                            \
    *(float4*)&sA[0][ar0][ac0] = make_float4(__uint_as_float(hx),          \
        __uint_as_float(hy), __uint_as_float(hz), __uint_as_float(hw));    \
    *(float4*)&sA[1][ar0][ac0] = make_float4(__uint_as_float(lx),          \
        __uint_as_float(ly), __uint_as_float(lz), __uint_as_float(lw));    \
    CVT_HILO(pa1.x,hx,lx) CVT_HILO(pa1.y,hy,ly)                            \
    CVT_HILO(pa1.z,hz,lz) CVT_HILO(pa1.w,hw,lw)                            \
    *(float4*)&sA[0][ar1][ac1] = make_float4(__uint_as_float(hx),          \
        __uint_as_float(hy), __uint_as_float(hz), __uint_as_float(hw));    \
    *(float4*)&sA[1][ar1][ac1] = make_float4(__uint_as_float(lx),          \
        __uint_as_float(ly), __uint_as_float(lz), __uint_as_float(lw));    \
    CVT_HILO(pb.x,hx,lx) CVT_HILO(pb.y,hy,ly)                              \
    CVT_HILO(pb.z,hz,lz) CVT_HILO(pb.w,hw,lw)                              \
    sB[0][bn4+0][bk] = __uint_as_float(hx); sB[1][bn4+0][bk] = __uint_as_float(lx); \
    sB[0][bn4+1][bk] = __uint_as_float(hy); sB[1][bn4+1][bk] = __uint_as_float(ly); \
    sB[0][bn4+2][bk] = __uint_as_float(hz); sB[1][bn4+2][bk] = __uint_as_float(lz); \
    sB[0][bn4+3][bk] = __uint_as_float(hw); sB[1][bn4+3][bk] = __uint_as_float(lw); }

    STAGE();
    __syncthreads();

    for (int c = 0; c < NC; c++) {
        if (c + 1 < NC) {
            pa0 = *(const float4*)(Ag0 + (c + 1) * 16);
            pa1 = *(const float4*)(Ag1 + (c + 1) * 16);
            pb  = *(const float4*)(Bg + (long)(c + 1) * 16 * Ncol);
        }

        #pragma unroll
        for (int fk = 0; fk < 2; fk++) {
            int kb = fk * 8;
            uint32_t Ah[2][4], Al[2][4], Bh[4][2], Bl[4][2];
            #pragma unroll
            for (int fm = 0; fm < 2; fm++) {
                const float* p0 = &sA[0][wm * 32 + fm * 16 + lr][kb + lc];
                const float* p1 = &sA[1][wm * 32 + fm * 16 + lr][kb + lc];
                Ah[fm][0] = __float_as_uint(p0[0]);
                Ah[fm][1] = __float_as_uint(p0[8 * 20]);
                Ah[fm][2] = __float_as_uint(p0[4]);
                Ah[fm][3] = __float_as_uint(p0[8 * 20 + 4]);
                Al[fm][0] = __float_as_uint(p1[0]);
                Al[fm][1] = __float_as_uint(p1[8 * 20]);
                Al[fm][2] = __float_as_uint(p1[4]);
                Al[fm][3] = __float_as_uint(p1[8 * 20 + 4]);
            }
            #pragma unroll
            for (int fn = 0; fn < 4; fn++) {
                const float* q0 = &sB[0][wn * 32 + fn * 8 + lr][kb + lc];
                const float* q1 = &sB[1][wn * 32 + fn * 8 + lr][kb + lc];
                Bh[fn][0] = __float_as_uint(q0[0]);
                Bh[fn][1] = __float_as_uint(q0[4]);
                Bl[fn][0] = __float_as_uint(q1[0]);
                Bl[fn][1] = __float_as_uint(q1[4]);
            }
            #pragma unroll
            for (int fm = 0; fm < 2; fm++)
                #pragma unroll
                for (int fn = 0; fn < 4; fn++) {
                    MMA8(acc[fm][fn], Ah[fm], Bh[fn]);
                    MMA8(acc[fm][fn], Ah[fm], Bl[fn]);
                    MMA8(acc[fm][fn], Al[fm], Bh[fn]);
                }
        }
        __syncthreads();
        if (c + 1 < NC) STAGE();
        __syncthreads();
    }
#undef STAGE

    // epilogue: c0/c1 -> (row, 2*lc+{0,1}); c2/c3 -> row+8
    #pragma unroll
    for (int fm = 0; fm < 2; fm++) {
        int r0 = rowBase + wm * 32 + fm * 16 + lr;
        #pragma unroll
        for (int fn = 0; fn < 4; fn++) {
            int cc = colBase + wn * 32 + fn * 8 + 2 * lc;
            float bx = 0.f, by = 0.f;
            if (bias) { bx = bias[cc] * bscale; by = bias[cc + 1] * bscale; }
            *(float2*)&C[(long)r0 * Ncol + cc] =
                make_float2(acc[fm][fn][0] + bx, acc[fm][fn][1] + by);
            *(float2*)&C[(long)(r0 + 8) * Ncol + cc] =
                make_float2(acc[fm][fn][2] + bx, acc[fm][fn][3] + by);
        }
    }
}

// ---------------- pairwise relu score PARTIAL kernel (R12, unchanged) ----------------
__global__ void __launch_bounds__(256) scores_k(const float* __restrict__ W2)
{
    const int BK = 16;
    const int KH = DD / 2;
    __shared__ __align__(16) float His[2][BK][APAD];
    __shared__ __align__(16) float Hjs[2][BK][64];
    __shared__ float w2s[KH];

    int b = blockIdx.z;
    int half = blockIdx.y >> 2;
    int nBase = (blockIdx.y & 3) * 64;
    int mBase = blockIdx.x * 64;
    int d0 = half * KH;

    int tid = threadIdx.x;
    int tx  = tid & 15;
    int tyr = tid >> 4;

    const float* hi = g_hihj + (long)b * NN * DD + d0;
    const float* hj = g_hihj + (long)SLAB_CD + (long)b * NN * DD + d0;
    if (tid < KH) w2s[tid] = W2[d0 + tid];

    int ar = tid >> 2, ac = (tid & 3) << 2;
    const float* Ip = hi + (long)(nBase + ar) * DD + ac;
    const float* Jp = hj + (long)(mBase + ar) * DD + ac;
    const int NC = KH / BK;

    u64 acc[2][4] = {};

    float4 i0 = *(const float4*)Ip;
    float4 j0 = *(const float4*)Jp;
    float4 i1 = *(const float4*)(Ip + BK);
    float4 j1 = *(const float4*)(Jp + BK);

    His[0][ac + 0][ar] = i0.x; His[0][ac + 1][ar] = i0.y;
    His[0][ac + 2][ar] = i0.z; His[0][ac + 3][ar] = i0.w;
    Hjs[0][ac + 0][ar] = j0.x; Hjs[0][ac + 1][ar] = j0.y;
    Hjs[0][ac + 2][ar] = j0.z; Hjs[0][ac + 3][ar] = j0.w;
    __syncthreads();

#define S_STEP(BUF, CC)                                                    \
    _Pragma("unroll")                                                      \
    for (int kk = 0; kk < BK; kk++) {                                      \
        ulonglong2 a = *(const ulonglong2*)&His[BUF][kk][tyr << 2];        \
        float4 j4 = *(const float4*)&Hjs[BUF][kk][tx << 2];                \
        u64 jd0 = dup2(j4.x), jd1 = dup2(j4.y);                            \
        u64 jd2 = dup2(j4.z), jd3 = dup2(j4.w);                            \
        u64 wd = dup2(w2s[(CC) * BK + kk]);                                \
        fma2(acc[0][0], relu2(add2(a.x, jd0)), wd);                        \
        fma2(acc[0][1], relu2(add2(a.x, jd1)), wd);                        \
        fma2(acc[0][2], relu2(add2(a.x, jd2)), wd);                        \
        fma2(acc[0][3], relu2(add2(a.x, jd3)), wd);                        \
        fma2(acc[1][0], relu2(add2(a.y, jd0)), wd);                        \
        fma2(acc[1][1], relu2(add2(a.y, jd1)), wd);                        \
        fma2(acc[1][2], relu2(add2(a.y, jd2)), wd);                        \
        fma2(acc[1][3], relu2(add2(a.y, jd3)), wd);                        \
    }

    for (int c = 0; c < NC; c += 2) {
        if (c + 2 < NC) {
            i0 = *(const float4*)(Ip + (c + 2) * BK);
            j0 = *(const float4*)(Jp + (c + 2) * BK);
        }
        His[1][ac + 0][ar] = i1.x; His[1][ac + 1][ar] = i1.y;
        His[1][ac + 2][ar] = i1.z; His[1][ac + 3][ar] = i1.w;
        Hjs[1][ac + 0][ar] = j1.x; Hjs[1][ac + 1][ar] = j1.y;
        Hjs[1][ac + 2][ar] = j1.z; Hjs[1][ac + 3][ar] = j1.w;
        S_STEP(0, c)
        __syncthreads();

        if (c + 3 < NC) {
            i1 = *(const float4*)(Ip + (c + 3) * BK);
            j1 = *(const float4*)(Jp + (c + 3) * BK);
        }
        if (c + 2 < NC) {
            His[0][ac + 0][ar] = i0.x; His[0][ac + 1][ar] = i0.y;
            His[0][ac + 2][ar] = i0.z; His[0][ac + 3][ar] = i0.w;
            Hjs[0][ac + 0][ar] = j0.x; Hjs[0][ac + 1][ar] = j0.y;
            Hjs[0][ac + 2][ar] = j0.z; Hjs[0][ac + 3][ar] = j0.w;
        }
        S_STEP(1, c + 1)
        __syncthreads();
    }
#undef S_STEP

    float* dst = g_scP + (long)half * SLAB_SC + (long)b * NN * NN;
    int n0 = nBase + (tyr << 2);
    int m0 = mBase + (tx << 2);

    #pragma unroll
    for (int p = 0; p < 2; p++) {
        float e0, o0, e1, o1, e2, o2, e3, o3;
        unpack2(acc[p][0], e0, o0); unpack2(acc[p][1], e1, o1);
        unpack2(acc[p][2], e2, o2); unpack2(acc[p][3], e3, o3);
        *(float4*)&dst[(long)(n0 + 2 * p + 0) * NN + m0] = make_float4(e0, e1, e2, e3);
        *(float4*)&dst[(long)(n0 + 2 * p + 1) * NN + m0] = make_float4(o0, o1, o2, o3);
    }
}

// ---------------- stats (R12, unchanged) ----------------
__global__ void __launch_bounds__(256) stats_k(const float* __restrict__ b2)
{
    int wid = threadIdx.x >> 5, lane = threadIdx.x & 31;
    int row = blockIdx.x * 8 + wid;
    float* p0 = g_scP + (long)row * NN;
    const float* p1 = g_scP + (long)SLAB_SC + (long)row * NN;
    float b2v = b2[0];
    int m0 = lane * 8;

    float4 u0 = *(const float4*)(p0 + m0);
    float4 u1 = *(const float4*)(p0 + m0 + 4);
    float4 v0 = *(const float4*)(p1 + m0);
    float4 v1 = *(const float4*)(p1 + m0 + 4);

    float s0 = u0.x + v0.x + b2v, s1 = u0.y + v0.y + b2v;
    float s2 = u0.z + v0.z + b2v, s3 = u0.w + v0.w + b2v;
    float s4 = u1.x + v1.x + b2v, s5 = u1.y + v1.y + b2v;
    float s6 = u1.z + v1.z + b2v, s7 = u1.w + v1.w + b2v;

    int n = row & (NN - 1);
    if (n == m0 + 0) s0 = 0.0f;  if (n == m0 + 1) s1 = 0.0f;
    if (n == m0 + 2) s2 = 0.0f;  if (n == m0 + 3) s3 = 0.0f;
    if (n == m0 + 4) s4 = 0.0f;  if (n == m0 + 5) s5 = 0.0f;
    if (n == m0 + 6) s6 = 0.0f;  if (n == m0 + 7) s7 = 0.0f;

    float mx = fmaxf(fmaxf(fmaxf(s0, s1), fmaxf(s2, s3)),
                     fmaxf(fmaxf(s4, s5), fmaxf(s6, s7)));
    #pragma unroll
    for (int o = 16; o > 0; o >>= 1) mx = fmaxf(mx, __shfl_xor_sync(0xffffffffu, mx, o));

    float e0 = __expf(s0 - mx), e1 = __expf(s1 - mx), e2 = __expf(s2 - mx), e3 = __expf(s3 - mx);
    float e4 = __expf(s4 - mx), e5 = __expf(s5 - mx), e6 = __expf(s6 - mx), e7 = __expf(s7 - mx);
    float s = e0 + e1 + e2 + e3 + e4 + e5 + e6 + e7;
    #pragma unroll
    for (int o = 16; o > 0; o >>= 1) s += __shfl_xor_sync(0xffffffffu, s, o);

    *(float4*)(p0 + m0)     = make_float4(e0, e1, e2, e3);
    *(float4*)(p0 + m0 + 4) = make_float4(e4, e5, e6, e7);
    if (lane == 0) g_inv[row] = 1.0f / s;
}

// ---------------- combine ctx halves + 1/sum (R12, unchanged) ----------------
__global__ void __launch_bounds__(256) combine_k()
{
    long e = ((long)blockIdx.x * 256 + threadIdx.x) * 4;
    int row = (int)(e >> 8);
    float inv = g_inv[row];
    float4 u = *(const float4*)(g_ctxP + e);
    float4 v = *(const float4*)(g_ctxP + (long)SLAB_CD + e);
    u.x = (u.x + v.x) * inv; u.y = (u.y + v.y) * inv;
    u.z = (u.z + v.z) * inv; u.w = (u.w + v.w) * inv;
    *(float4*)(g_ctxP + e) = u;
}

// ---------------- combine proj halves + bias + LN + residual (R12) ----------------
__global__ void __launch_bounds__(256) ln_res_k(
    const float* __restrict__ x,
    const float* __restrict__ bp,
    const float* __restrict__ gamma,
    const float* __restrict__ beta,
    float* __restrict__ out)
{
    __shared__ float red[8];
    int row = blockIdx.x;
    int tid = threadIdx.x;
    int wid = tid >> 5, lane = tid & 31;

    float p = g_projP[(long)row * DD + tid]
            + g_projP[(long)SLAB_CD + (long)row * DD + tid]
            + bp[tid];

    float s = p;
    #pragma unroll
    for (int o = 16; o > 0; o >>= 1) s += __shfl_xor_sync(0xffffffffu, s, o);
    if (lane == 0) red[wid] = s;
    __syncthreads();
    float tot = 0.0f;
    #pragma unroll
    for (int w = 0; w < 8; w++) tot += red[w];
    float mean = tot * (1.0f / DD);

    float dv = p - mean;
    float q = dv * dv;
    #pragma unroll
    for (int o = 16; o > 0; o >>= 1) q += __shfl_xor_sync(0xffffffffu, q, o);
    __syncthreads();
    if (lane == 0) red[wid] = q;
    __syncthreads();
    float tq = 0.0f;
    #pragma unroll
    for (int w = 0; w < 8; w++) tq += red[w];
    float var = tq * (1.0f / DD);

    float inv = rsqrtf(var + LN_EPS);
    out[(long)row * DD + tid] = x[(long)row * DD + tid] + dv * inv * gamma[tid] + beta[tid];
}

// ---------------- launch ----------------
extern "C" void kernel_launch(void* const* d_in, const int* in_sizes, int n_in,
                              void* d_out, int out_size)
{
    const float* x     = (const float*)d_in[0];
    const float* W1    = (const float*)d_in[1];
    const float* b1    = (const float*)d_in[2];
    const float* W2    = (const float*)d_in[3];
    const float* b2    = (const float*)d_in[4];
    const float* Wp    = (const float*)d_in[5];
    const float* bp    = (const float*)d_in[6];
    const float* gamma = (const float*)d_in[7];
    const float* beta  = (const float*)d_in[8];
    float* out = (float*)d_out;

    float *hihj, *scP, *ctxP, *projP;
    cudaGetSymbolAddress((void**)&hihj,  g_hihj);
    cudaGetSymbolAddress((void**)&scP,   g_scP);
    cudaGetSymbolAddress((void**)&ctxP,  g_ctxP);
    cudaGetSymbolAddress((void**)&projP, g_projP);

    // 1) hi'/hj' = x @ W1 halves + 0.5*b1        (tensor, grid 16x4x2 = 128)
    gemm_t<<<dim3(16, 4, 2), 256>>>(
        x, 0L, DD, W1, (long)DD * DD, hihj, (long)SLAB_CD, 0L,
        b1, 0.5f, DD, DD, 0);

    // 2) score partials, d split                  (grid 4x8x8 = 256)
    scores_k<<<dim3(4, 8, 8), 256>>>(W2);

    // 3) combine + b2 + diag + exp + 1/sum        (grid 256)
    stats_k<<<(BSZ * NN) / 8, 256>>>(b2);

    // 4) ctx partials = exp'd @ x, m split        (tensor, grid 2x8x8 = 128)
    gemm_t<<<dim3(2, 8, 8), 256>>>(
        scP, (long)NN * NN, NN, x, (long)NN * DD,
        ctxP, (long)NN * DD, (long)SLAB_CD,
        nullptr, 0.0f, NN / 2, DD, 1);

    // 5) combine ctx halves * inv                 (grid 512)
    combine_k<<<(BSZ * NN * DD) / (256 * 4), 256>>>();

    // 6) proj partials = ctx @ Wp, k split        (tensor, grid 16x8x1 = 128)
    gemm_t<<<dim3(16, 8, 1), 256>>>(
        ctxP, 0L, DD, Wp, 0L,
        projP, 0L, (long)SLAB_CD,
        nullptr, 0.0f, DD / 2, DD, 1);

    // 7) combine proj halves + bp + LN + residual (grid 2048)
    ln_res_k<<<BSZ * NN, 256>>>(x, bp, gamma, beta, out);
}